// round 2
// baseline (speedup 1.0000x reference)
#include <cuda_runtime.h>
#include <math.h>

#define BATCH 128
#define N 512
#define NB 16            // GJ block size
#define INV_THREADS 256

// Scratch (static __device__ arrays; no allocation in kernel_launch)
__device__ float g_A[(size_t)BATCH * N * N];   // permuted Laplacian -> its inverse
__device__ float g_diag[BATCH * N];            // inv[j][j] (original indexing)
__device__ float g_col0[BATCH * N];            // inv[j][0]

// ---------------------------------------------------------------------------
// Build L'' = P L P^T into g_A, where P moves index 0 (root) to the end.
// new index p corresponds to old index (p+1) mod N; writes use
// ni = (i+N-1) & (N-1).  Padded region is exact identity.
// ---------------------------------------------------------------------------
__global__ void __launch_bounds__(512) build_kernel(const float* __restrict__ x,
                                                    const int* __restrict__ lengths) {
    int b = blockIdx.x;
    int lx = lengths[b];
    const float* xb = x + (size_t)b * N * N;
    float* A = g_A + (size_t)b * N * N;
    __shared__ float colsum[N];

    int j = threadIdx.x;
    float s = 0.f;
    if (j < lx) {
        for (int i = 0; i < lx; i++) {
            if (i != j) s += expf(xb[(size_t)i * N + j]);
        }
    }
    colsum[j] = s;
    __syncthreads();

    int nj = (j + N - 1) & (N - 1);
    for (int i = 0; i < N; i++) {
        float val;
        if (i < lx && j < lx) {
            if (i == 0)       val = expf(xb[(size_t)j * N + j]);     // root row
            else if (i == j)  val = colsum[j];
            else              val = -expf(xb[(size_t)i * N + j]);
        } else {
            val = (i == j) ? 1.f : 0.f;                              // identity padding
        }
        int ni = (i + N - 1) & (N - 1);
        A[(size_t)ni * N + nj] = val;
    }
}

// ---------------------------------------------------------------------------
// In-place blocked Gauss-Jordan inversion, no pivoting. One CTA per matrix.
// Per block step: panel (512 x 16) GJ in smem, then rank-16 GEMM update of all
// other columns with R (original panel rows) held in registers.
// ---------------------------------------------------------------------------
__global__ void __launch_bounds__(INV_THREADS) gj_invert_kernel() {
    int b = blockIdx.x;
    float* A = g_A + (size_t)b * N * N;

    __shared__ float P[N][NB + 1];   // 512 x 17 floats = 34.8 KB, pad kills conflicts
    __shared__ float prow[NB];

    int tid = threadIdx.x;                 // 0..255
    int jg  = tid & 127;                   // float4 column group (128 groups)
    int rh  = tid >> 7;                    // row half: 0 -> rows [0,256), 1 -> [256,512)

    for (int K = 0; K < N; K += NB) {
        bool jInPanel = ((unsigned)(jg * 4 - K) < (unsigned)NB);

        // ---- load panel columns into smem, and R rows into registers ----
        for (int i = tid; i < N; i += INV_THREADS) {
            const float4* src = (const float4*)(A + (size_t)i * N + K);
            #pragma unroll
            for (int q = 0; q < 4; q++) {
                float4 v = src[q];
                P[i][4 * q + 0] = v.x; P[i][4 * q + 1] = v.y;
                P[i][4 * q + 2] = v.z; P[i][4 * q + 3] = v.w;
            }
        }
        float4 Rreg[NB];
        if (!jInPanel) {
            #pragma unroll
            for (int m = 0; m < NB; m++)
                Rreg[m] = *(const float4*)(A + (size_t)(K + m) * N + jg * 4);
            // Force HW completion of these loads before any barrier is passed:
            float chk = 0.f;
            #pragma unroll
            for (int m = 0; m < NB; m++) chk += Rreg[m].x + Rreg[m].w;
            if (chk == 1.2345678e30f) prow[0] = chk;   // never taken; creates dependency
        } else {
            #pragma unroll
            for (int m = 0; m < NB; m++) Rreg[m] = make_float4(0.f, 0.f, 0.f, 0.f);
        }
        __syncthreads();

        // ---- phase 1: 16 scalar GJ steps restricted to the panel (in smem) ----
        for (int m = 0; m < NB; m++) {
            int pr = K + m;
            if (tid < NB) {
                float pv   = P[pr][m];
                float pinv = 1.0f / pv;
                prow[tid] = (tid == m) ? pinv : P[pr][tid] * pinv;
            }
            __syncthreads();
            for (int i = tid; i < N; i += INV_THREADS) {
                if (i != pr) {
                    float f = P[i][m];
                    #pragma unroll
                    for (int c = 0; c < NB; c++) {
                        float upd = P[i][c] - f * prow[c];
                        P[i][c] = (c == m) ? (-f * prow[m]) : upd;
                    }
                }
            }
            if (tid < NB) P[pr][tid] = prow[tid];
            __syncthreads();
        }

        // ---- write final panel columns back to global ----
        for (int i = tid; i < N; i += INV_THREADS) {
            float4* dst = (float4*)(A + (size_t)i * N + K);
            #pragma unroll
            for (int q = 0; q < 4; q++)
                dst[q] = make_float4(P[i][4 * q + 0], P[i][4 * q + 1],
                                     P[i][4 * q + 2], P[i][4 * q + 3]);
        }
        __syncthreads();

        // ---- phase 3: rank-16 update of all non-panel columns ----
        // A[i,j] += sum_m Pf[i,m] * R[m,j]   (panel rows: overwrite, acc starts 0)
        if (!jInPanel) {
            float* base = A + (size_t)(rh * 256) * N + jg * 4;
            float4 nxt = *(const float4*)base;
            for (int ii = 0; ii < 256; ii++) {
                int i = rh * 256 + ii;
                float4 cur = nxt;
                if (ii < 255) nxt = *(const float4*)(base + (size_t)(ii + 1) * N);
                float4 acc = ((unsigned)(i - K) < (unsigned)NB)
                                 ? make_float4(0.f, 0.f, 0.f, 0.f) : cur;
                #pragma unroll
                for (int m = 0; m < NB; m++) {
                    float f = P[i][m];
                    acc.x = fmaf(f, Rreg[m].x, acc.x);
                    acc.y = fmaf(f, Rreg[m].y, acc.y);
                    acc.z = fmaf(f, Rreg[m].z, acc.z);
                    acc.w = fmaf(f, Rreg[m].w, acc.w);
                }
                *(float4*)(base + (size_t)ii * N) = acc;
            }
        }
        __syncthreads();
    }
}

// ---------------------------------------------------------------------------
// Extract inv[j][j] and inv[j][0] in ORIGINAL indexing from the permuted inverse.
// inv(L)[a][b] = g_A[(a+N-1)%N][(b+N-1)%N];  original col 0 -> permuted col N-1.
// ---------------------------------------------------------------------------
__global__ void diag_kernel() {
    int b = blockIdx.x;
    int j = threadIdx.x;
    const float* A = g_A + (size_t)b * N * N;
    int nj = (j + N - 1) & (N - 1);
    g_diag[b * N + j] = A[(size_t)nj * N + nj];
    g_col0[b * N + j] = A[(size_t)nj * N + (N - 1)];
}

// ---------------------------------------------------------------------------
// out[i,j] = mask * ( e*invdiag[j]*(j>0) - e*inv[j][i]*(i>0) + (i==j)*e*inv[j][0] )
// 32x32 tiles; inv^T gathered through an smem transpose tile.
// ---------------------------------------------------------------------------
__global__ void __launch_bounds__(256) output_kernel(const float* __restrict__ x,
                                                     const int* __restrict__ lengths,
                                                     float* __restrict__ out) {
    int jt = blockIdx.x, it = blockIdx.y, b = blockIdx.z;
    __shared__ float T[32][33];
    const float* A  = g_A + (size_t)b * N * N;
    const float* xb = x   + (size_t)b * N * N;
    float* ob = out + (size_t)b * N * N;
    int lx = lengths[b];

    int tx = threadIdx.x & 31;
    int ty = threadIdx.x >> 5;     // 0..7

    // T[r][c] = inv[jt*32+r][it*32+c]
    for (int r = ty; r < 32; r += 8) {
        int j = jt * 32 + r;
        int i = it * 32 + tx;
        int nj = (j + N - 1) & (N - 1);
        int ni = (i + N - 1) & (N - 1);
        T[r][tx] = A[(size_t)nj * N + ni];
    }
    __syncthreads();

    for (int r = ty; r < 32; r += 8) {
        int i = it * 32 + r;
        int j = jt * 32 + tx;
        float v = 0.f;
        if (i < lx && j < lx) {
            float e  = expf(xb[(size_t)i * N + j]);
            float t1 = (j > 0) ? e * g_diag[b * N + j] : 0.f;
            float t2 = (i > 0) ? e * T[tx][r] : 0.f;   // inv[j][i]
            v = t1 - t2;
            if (i == j) v += e * g_col0[b * N + j];    // roots on the diagonal
        }
        ob[(size_t)i * N + j] = v;
    }
}

// ---------------------------------------------------------------------------
extern "C" void kernel_launch(void* const* d_in, const int* in_sizes, int n_in,
                              void* d_out, int out_size) {
    const float* x       = (const float*)d_in[0];
    const int*   lengths = (const int*)d_in[1];
    float*       out     = (float*)d_out;

    build_kernel<<<BATCH, 512>>>(x, lengths);
    gj_invert_kernel<<<BATCH, INV_THREADS>>>();
    diag_kernel<<<BATCH, N>>>();
    output_kernel<<<dim3(16, 16, BATCH), 256>>>(x, lengths, out);
}

// round 5
// speedup vs baseline: 1.5037x; 1.5037x over previous
#include <cuda_runtime.h>
#include <math.h>

#define BATCH 128
#define N 512
#define NB 32             // GJ block size (panel width)
#define INV_THREADS 512   // one row per thread in phase 1

// Scratch (static __device__ arrays; no allocation anywhere)
__device__ float g_A[(size_t)BATCH * N * N];   // permuted Laplacian -> its inverse
__device__ float g_R[(size_t)BATCH * NB * N];  // per-K-step snapshot of panel rows
__device__ float g_diag[BATCH * N];            // inv[j][j] (original indexing)
__device__ float g_col0[BATCH * N];            // inv[j][0]

// ---------------------------------------------------------------------------
// Build L'' = P L P^T into g_A, where P moves index 0 (root) to the end.
// new index p corresponds to old index (p+1) mod N. Padded region = identity.
// ---------------------------------------------------------------------------
__global__ void __launch_bounds__(512) build_kernel(const float* __restrict__ x,
                                                    const int* __restrict__ lengths) {
    int b = blockIdx.x;
    int lx = lengths[b];
    const float* xb = x + (size_t)b * N * N;
    float* A = g_A + (size_t)b * N * N;
    __shared__ float colsum[N];

    int j = threadIdx.x;
    float s = 0.f;
    if (j < lx) {
        for (int i = 0; i < lx; i++) {
            if (i != j) s += expf(xb[(size_t)i * N + j]);
        }
    }
    colsum[j] = s;
    __syncthreads();

    int nj = (j + N - 1) & (N - 1);
    for (int i = 0; i < N; i++) {
        float val;
        if (i < lx && j < lx) {
            if (i == 0)       val = expf(xb[(size_t)j * N + j]);     // root row
            else if (i == j)  val = colsum[j];
            else              val = -expf(xb[(size_t)i * N + j]);
        } else {
            val = (i == j) ? 1.f : 0.f;                              // identity padding
        }
        int ni = (i + N - 1) & (N - 1);
        A[(size_t)ni * N + nj] = val;
    }
}

// ---------------------------------------------------------------------------
// In-place blocked Gauss-Jordan inversion, no pivoting (permuted matrix is
// strictly column-diagonally-dominant in its leading block; root row last;
// padded rows are exact identity). One CTA per matrix.
//
// Per K-step:
//   0) snapshot original panel rows A[K..K+NB-1][:] -> g_R     (global scratch)
//   1) NB scalar GJ steps on panel columns; each thread holds its own panel
//      row in registers; pivot row broadcast via a 2x32-float smem buffer.
//   2) write final panel columns back to A
//   3) rank-NB update of non-panel columns; P re-read from A (warp-uniform,
//      L1 broadcast), R from g_R (L1-resident).
// ---------------------------------------------------------------------------
__global__ void __launch_bounds__(INV_THREADS) gj_invert_kernel() {
    int b = blockIdx.x;
    float* A  = g_A + (size_t)b * N * N;
    float* Rg = g_R + (size_t)b * NB * N;

    __shared__ float prow[2][NB];

    int tid = threadIdx.x;                 // 0..511
    int jg  = tid & 127;                   // float4 column group (128 groups)
    int q   = tid >> 7;                    // row quarter: rows [q*128, q*128+128)

    for (int K = 0; K < N; K += NB) {
        bool jInPanel = ((unsigned)(jg * 4 - K) < (unsigned)NB);

        // ---- 0) snapshot R rows (K..K+NB-1, full width) to global scratch ----
        {
            int m  = tid >> 4;             // 0..31
            int cg = (tid & 15) * 8;       // 8 float4 groups per thread
            const float4* src = (const float4*)(A + (size_t)(K + m) * N);
            float4* dst = (float4*)(Rg + (size_t)m * N);
            #pragma unroll
            for (int u = 0; u < 8; u++)
                dst[cg + u] = src[cg + u];
        }

        // ---- load own panel row into registers ----
        float row[NB];
        {
            const float4* psrc = (const float4*)(A + (size_t)tid * N + K);
            #pragma unroll
            for (int qq = 0; qq < NB / 4; qq++) {
                float4 v = psrc[qq];
                row[4 * qq + 0] = v.x; row[4 * qq + 1] = v.y;
                row[4 * qq + 2] = v.z; row[4 * qq + 3] = v.w;
            }
        }
        __syncthreads();   // snapshot complete before any panel rewrite below

        // ---- 1) NB GJ steps; pivot row broadcast via double-buffered smem ----
        #pragma unroll
        for (int m = 0; m < NB; m++) {
            int pr = K + m;
            int buf = m & 1;
            if (tid == pr) {
                float pinv = __fdividef(1.0f, row[m]);
                #pragma unroll
                for (int c = 0; c < NB; c++) {
                    float sv = (c == m) ? pinv : row[c] * pinv;
                    row[c] = sv;
                    prow[buf][c] = sv;
                }
            }
            __syncthreads();
            if (tid != pr) {
                float f = row[m];
                #pragma unroll
                for (int c = 0; c < NB; c++) {
                    float upd = row[c] - f * prow[buf][c];
                    row[c] = (c == m) ? (-f * prow[buf][m]) : upd;
                }
            }
        }

        // ---- 2) write final panel columns back to global ----
        {
            float4* pdst = (float4*)(A + (size_t)tid * N + K);
            #pragma unroll
            for (int qq = 0; qq < NB / 4; qq++)
                pdst[qq] = make_float4(row[4 * qq + 0], row[4 * qq + 1],
                                       row[4 * qq + 2], row[4 * qq + 3]);
        }
        __syncthreads();   // panel visible to all threads before phase 3

        // ---- 3) rank-NB update of all non-panel columns ----
        // A[i,j] += sum_m Pf[i,m] * R[m,j]; panel rows overwritten (acc from 0).
        if (!jInPanel) {
            float* base = A + (size_t)(q * 128) * N + jg * 4;
            const float4* Rj = (const float4*)(Rg + jg * 4);      // stride N/4
            #pragma unroll 1
            for (int chunk = 0; chunk < 16; chunk++) {
                int i0 = q * 128 + chunk * 8;
                float4 acc[8];
                #pragma unroll
                for (int r = 0; r < 8; r++) {
                    float4 cur = *(const float4*)(base + (size_t)(chunk * 8 + r) * N);
                    bool inPanel = ((unsigned)(i0 + r - K) < (unsigned)NB);
                    acc[r] = inPanel ? make_float4(0.f, 0.f, 0.f, 0.f) : cur;
                }
                #pragma unroll
                for (int mg = 0; mg < NB / 4; mg++) {
                    float4 rv0 = Rj[(4 * mg + 0) * (N / 4)];
                    float4 rv1 = Rj[(4 * mg + 1) * (N / 4)];
                    float4 rv2 = Rj[(4 * mg + 2) * (N / 4)];
                    float4 rv3 = Rj[(4 * mg + 3) * (N / 4)];
                    #pragma unroll
                    for (int r = 0; r < 8; r++) {
                        // warp-uniform load of P[i0+r][4mg..4mg+3] (L1 broadcast)
                        float4 pv = *(const float4*)(A + (size_t)(i0 + r) * N + K + 4 * mg);
                        acc[r].x = fmaf(pv.x, rv0.x, acc[r].x);
                        acc[r].y = fmaf(pv.x, rv0.y, acc[r].y);
                        acc[r].z = fmaf(pv.x, rv0.z, acc[r].z);
                        acc[r].w = fmaf(pv.x, rv0.w, acc[r].w);
                        acc[r].x = fmaf(pv.y, rv1.x, acc[r].x);
                        acc[r].y = fmaf(pv.y, rv1.y, acc[r].y);
                        acc[r].z = fmaf(pv.y, rv1.z, acc[r].z);
                        acc[r].w = fmaf(pv.y, rv1.w, acc[r].w);
                        acc[r].x = fmaf(pv.z, rv2.x, acc[r].x);
                        acc[r].y = fmaf(pv.z, rv2.y, acc[r].y);
                        acc[r].z = fmaf(pv.z, rv2.z, acc[r].z);
                        acc[r].w = fmaf(pv.z, rv2.w, acc[r].w);
                        acc[r].x = fmaf(pv.w, rv3.x, acc[r].x);
                        acc[r].y = fmaf(pv.w, rv3.y, acc[r].y);
                        acc[r].z = fmaf(pv.w, rv3.z, acc[r].z);
                        acc[r].w = fmaf(pv.w, rv3.w, acc[r].w);
                    }
                }
                #pragma unroll
                for (int r = 0; r < 8; r++)
                    *(float4*)(base + (size_t)(chunk * 8 + r) * N) = acc[r];
            }
        }
        __syncthreads();
    }
}

// ---------------------------------------------------------------------------
// Extract inv[j][j] and inv[j][0] in ORIGINAL indexing from the permuted inverse.
// inv(L)[a][b] = g_A[(a+N-1)%N][(b+N-1)%N];  original col 0 -> permuted col N-1.
// ---------------------------------------------------------------------------
__global__ void diag_kernel() {
    int b = blockIdx.x;
    int j = threadIdx.x;
    const float* A = g_A + (size_t)b * N * N;
    int nj = (j + N - 1) & (N - 1);
    g_diag[b * N + j] = A[(size_t)nj * N + nj];
    g_col0[b * N + j] = A[(size_t)nj * N + (N - 1)];
}

// ---------------------------------------------------------------------------
// out[i,j] = mask * ( e*invdiag[j]*(j>0) - e*inv[j][i]*(i>0) + (i==j)*e*inv[j][0] )
// ---------------------------------------------------------------------------
__global__ void __launch_bounds__(256) output_kernel(const float* __restrict__ x,
                                                     const int* __restrict__ lengths,
                                                     float* __restrict__ out) {
    int jt = blockIdx.x, it = blockIdx.y, b = blockIdx.z;
    __shared__ float T[32][33];
    const float* A  = g_A + (size_t)b * N * N;
    const float* xb = x   + (size_t)b * N * N;
    float* ob = out + (size_t)b * N * N;
    int lx = lengths[b];

    int tx = threadIdx.x & 31;
    int ty = threadIdx.x >> 5;     // 0..7

    // T[r][c] = inv[jt*32+r][it*32+c]
    for (int r = ty; r < 32; r += 8) {
        int j = jt * 32 + r;
        int i = it * 32 + tx;
        int nj = (j + N - 1) & (N - 1);
        int ni = (i + N - 1) & (N - 1);
        T[r][tx] = A[(size_t)nj * N + ni];
    }
    __syncthreads();

    for (int r = ty; r < 32; r += 8) {
        int i = it * 32 + r;
        int j = jt * 32 + tx;
        float v = 0.f;
        if (i < lx && j < lx) {
            float e  = expf(xb[(size_t)i * N + j]);
            float t1 = (j > 0) ? e * g_diag[b * N + j] : 0.f;
            float t2 = (i > 0) ? e * T[tx][r] : 0.f;   // inv[j][i]
            v = t1 - t2;
            if (i == j) v += e * g_col0[b * N + j];    // roots on the diagonal
        }
        ob[(size_t)i * N + j] = v;
    }
}

// ---------------------------------------------------------------------------
extern "C" void kernel_launch(void* const* d_in, const int* in_sizes, int n_in,
                              void* d_out, int out_size) {
    const float* x       = (const float*)d_in[0];
    const int*   lengths = (const int*)d_in[1];
    float*       out     = (float*)d_out;

    build_kernel<<<BATCH, 512>>>(x, lengths);
    gj_invert_kernel<<<BATCH, INV_THREADS>>>();
    diag_kernel<<<BATCH, N>>>();
    output_kernel<<<dim3(16, 16, BATCH), 256>>>(x, lengths, out);
}